// round 1
// baseline (speedup 1.0000x reference)
#include <cuda_runtime.h>
#include <cstdint>

// Problem constants
#define BB 2
#define LL 4096
#define DD 1024
#define HH 16
#define DH 64
#define GG 256
#define HD 1024   // H*dh

// ---------------------------------------------------------------------------
// Scratch (device globals; allocation inside kernel_launch is forbidden)
// ---------------------------------------------------------------------------
__device__ float g_q [BB*HH*LL*DH];   // [B,H,L,dh]  (pre-scaled by 1/8)
__device__ float g_k [BB*HH*LL*DH];   // [B,H,L,dh]
__device__ float g_v [BB*HH*LL*DH];   // [B,H,L,dh]
__device__ float g_sk[BB*HH*GG*DH];   // [B,H,G,dh]
__device__ float g_sv[BB*HH*GG*DH];   // [B,H,G,dh]
__device__ float g_g [BB*GG*DD];      // [B,G,D]  block sums of x
__device__ float g_y [BB*LL*HD];      // [B,L,H*dh] attention output

// ---------------------------------------------------------------------------
// Helpers
// ---------------------------------------------------------------------------
__device__ __forceinline__ float tf32r(float x) {
    // round-to-nearest tf32 (removes truncation bias of the HMMA unit)
    uint32_t u;
    asm("cvt.rna.tf32.f32 %0, %1;" : "=r"(u) : "f"(x));
    return __uint_as_float(u);
}

__device__ __forceinline__ void mma_tf32(float* c,
                                         float a0, float a1, float a2, float a3,
                                         float b0, float b1) {
    asm volatile(
        "mma.sync.aligned.m16n8k8.row.col.f32.tf32.tf32.f32 "
        "{%0,%1,%2,%3}, {%4,%5,%6,%7}, {%8,%9}, {%0,%1,%2,%3};\n"
        : "+f"(c[0]), "+f"(c[1]), "+f"(c[2]), "+f"(c[3])
        : "r"(__float_as_uint(a0)), "r"(__float_as_uint(a1)),
          "r"(__float_as_uint(a2)), "r"(__float_as_uint(a3)),
          "r"(__float_as_uint(b0)), "r"(__float_as_uint(b1)));
}

// ---------------------------------------------------------------------------
// Kernel 1: g[b,gb,d] = sum_{t<16} x[b, gb*16+t, d]
// ---------------------------------------------------------------------------
__global__ void k_gsum(const float* __restrict__ x) {
    int idx = blockIdx.x * blockDim.x + threadIdx.x;     // 524288 threads
    int d   = idx & 1023;
    int row = idx >> 10;            // b*256 + gb
    int b   = row >> 8;
    int gb  = row & 255;
    const float* xp = x + ((size_t)b * LL + gb * 16) * DD + d;
    float s = 0.f;
#pragma unroll
    for (int t = 0; t < 16; t++) s += xp[(size_t)t * DD];
    g_g[idx] = s;
}

// ---------------------------------------------------------------------------
// tf32 GEMM, 128x128x16 tiles, 8 warps (4x2), warp tile 32x64.
// MODE 0: A = [x ; g] (M=8704, K=1024), B = [Wq|Wk|Wv] (N=3072),
//         epilogue scatters into g_q/g_k/g_v/g_sk/g_sv ([B,H,L,dh] layouts),
//         q scaled by 1/8.
// MODE 1: A = g_y (M=8192), B = Wo (N=1024), epilogue -> Out.
// ---------------------------------------------------------------------------
template<int MODE>
__global__ void __launch_bounds__(256)
gemm_tf32(const float* __restrict__ X,
          const float* __restrict__ W0,
          const float* __restrict__ W1,
          const float* __restrict__ W2,
          float* __restrict__ Out)
{
    __shared__ float As[2][16][136];   // [k][m], stride 136 ≡ 8 (mod 32): conflict-free frags
    __shared__ float Bs[2][16][136];   // [k][n]

    const int bn = blockIdx.x, bm = blockIdx.y;
    const int tid  = threadIdx.x;
    const int warp = tid >> 5, lane = tid & 31;
    const int lq = lane >> 2, lr = lane & 3;
    const int wm = warp >> 1, wn = warp & 1;

    const int mbase = bm * 128;
    const int nbase = bn * 128;

    const float* Aptr;
    const float* Wp;
    int which = 0;
    if (MODE == 0) {
        Aptr = (mbase < 8192) ? (X + (size_t)mbase * DD)
                              : (g_g + (size_t)(mbase - 8192) * DD);
        which = nbase >> 10;
        Wp = (which == 0) ? W0 : (which == 1) ? W1 : W2;
        Wp += (nbase & 1023);
    } else {
        Aptr = g_y + (size_t)mbase * HD;
        Wp   = W0 + nbase;
    }

    float c[2][8][4];
#pragma unroll
    for (int i = 0; i < 2; i++)
#pragma unroll
        for (int j = 0; j < 8; j++)
#pragma unroll
            for (int e = 0; e < 4; e++) c[i][j][e] = 0.f;

    const int am  = tid >> 2;           // 0..63
    const int ak  = (tid & 3) << 2;     // 0,4,8,12
    const int bk  = tid >> 5;           // 0..7
    const int bn4 = (tid & 31) << 2;    // 0..124

    float4 ra0, ra1, rb0, rb1;

#define LDG_TILE(kt) do {                                                     \
        const float* ap = Aptr + (kt) * 16;                                   \
        ra0 = *(const float4*)(ap + (size_t)am * 1024 + ak);                  \
        ra1 = *(const float4*)(ap + (size_t)(am + 64) * 1024 + ak);           \
        const float* bp = Wp + (size_t)((kt) * 16) * 1024;                    \
        rb0 = *(const float4*)(bp + (size_t)bk * 1024 + bn4);                 \
        rb1 = *(const float4*)(bp + (size_t)(bk + 8) * 1024 + bn4);           \
    } while (0)

#define STS_TILE(buf) do {                                                    \
        const float* pa0 = (const float*)&ra0;                                \
        const float* pa1 = (const float*)&ra1;                                \
        _Pragma("unroll")                                                     \
        for (int j = 0; j < 4; j++) {                                         \
            As[buf][ak + j][am]      = tf32r(pa0[j]);                         \
            As[buf][ak + j][am + 64] = tf32r(pa1[j]);                         \
        }                                                                     \
        float4 tb0, tb1;                                                      \
        tb0.x = tf32r(rb0.x); tb0.y = tf32r(rb0.y);                           \
        tb0.z = tf32r(rb0.z); tb0.w = tf32r(rb0.w);                           \
        tb1.x = tf32r(rb1.x); tb1.y = tf32r(rb1.y);                           \
        tb1.z = tf32r(rb1.z); tb1.w = tf32r(rb1.w);                           \
        *(float4*)&Bs[buf][bk][bn4]     = tb0;                                \
        *(float4*)&Bs[buf][bk + 8][bn4] = tb1;                                \
    } while (0)

    const int NK = 64;                   // K = 1024 / 16
    LDG_TILE(0);
    STS_TILE(0);
    __syncthreads();

    for (int kt = 0; kt < NK; kt++) {
        const int buf = kt & 1;
        if (kt + 1 < NK) LDG_TILE(kt + 1);

#pragma unroll
        for (int ks = 0; ks < 2; ks++) {
            float a[2][4], bfr[8][2];
#pragma unroll
            for (int mi = 0; mi < 2; mi++) {
                int r = wm * 32 + mi * 16 + lq;
                a[mi][0] = As[buf][ks * 8 + lr][r];
                a[mi][1] = As[buf][ks * 8 + lr][r + 8];
                a[mi][2] = As[buf][ks * 8 + lr + 4][r];
                a[mi][3] = As[buf][ks * 8 + lr + 4][r + 8];
            }
#pragma unroll
            for (int nj = 0; nj < 8; nj++) {
                int cc = wn * 64 + nj * 8 + lq;
                bfr[nj][0] = Bs[buf][ks * 8 + lr][cc];
                bfr[nj][1] = Bs[buf][ks * 8 + lr + 4][cc];
            }
#pragma unroll
            for (int mi = 0; mi < 2; mi++)
#pragma unroll
                for (int nj = 0; nj < 8; nj++)
                    mma_tf32(c[mi][nj], a[mi][0], a[mi][1], a[mi][2], a[mi][3],
                             bfr[nj][0], bfr[nj][1]);
        }

        if (kt + 1 < NK) {
            STS_TILE(buf ^ 1);
            __syncthreads();
        }
    }
#undef LDG_TILE
#undef STS_TILE

    // -------------------------- epilogue --------------------------
#pragma unroll
    for (int mi = 0; mi < 2; mi++)
#pragma unroll
        for (int e2 = 0; e2 < 2; e2++) {
            int gm = mbase + wm * 32 + mi * 16 + lq + e2 * 8;
#pragma unroll
            for (int nj = 0; nj < 8; nj++) {
                float v0 = c[mi][nj][e2 * 2 + 0];
                float v1 = c[mi][nj][e2 * 2 + 1];
                if (MODE == 1) {
                    int gn = nbase + wn * 64 + nj * 8 + 2 * lr;
                    float2 o; o.x = v0; o.y = v1;
                    *(float2*)(Out + (size_t)gm * 1024 + gn) = o;
                } else {
                    int cc = (nbase & 1023) + wn * 64 + nj * 8 + 2 * lr;
                    int h  = cc >> 6;
                    int chc = cc & 63;
                    if (gm < 8192) {
                        int b = gm >> 12, l = gm & 4095;
                        float s = (which == 0) ? 0.125f : 1.0f;
                        float* dst = (which == 0) ? g_q : (which == 1) ? g_k : g_v;
                        dst += ((size_t)(b * HH + h) * LL + l) * DH + chc;
                        float2 o; o.x = v0 * s; o.y = v1 * s;
                        *(float2*)dst = o;
                    } else if (which != 0) {
                        int gb = gm - 8192;
                        int b = gb >> 8, gp = gb & 255;
                        float* dst = (which == 1) ? g_sk : g_sv;
                        dst += ((size_t)(b * HH + h) * GG + gp) * DH + chc;
                        float2 o; o.x = v0; o.y = v1;
                        *(float2*)dst = o;
                    }
                }
            }
        }
}

// ---------------------------------------------------------------------------
// Kernel 3: attention.  One CTA per (block n, head h, batch b).
// 8 warps x 16 query rows.  5 key chunks of 128 (prev/cur/next local + 2 side).
// Flash-style online softmax; extra logit handled exactly via
//   y = acc / (d + exp(-running_max)).
// ---------------------------------------------------------------------------
#define KS_STRIDE 72     // 64 + 8  (≡ 8 mod 32 -> conflict-free B frags)
#define PS_STRIDE 136    // 128 + 8
#define ATTN_SMEM_BYTES ((128*KS_STRIDE*2 + 128*PS_STRIDE) * 4)

__global__ void __launch_bounds__(256, 1)
attn_kernel()
{
    extern __shared__ float sm[];
    float* Ks = sm;                        // [128][72]
    float* Vs = sm + 128 * KS_STRIDE;      // [128][72]
    float* Ps = Vs + 128 * KS_STRIDE;      // [128][136]

    const int n = blockIdx.x, h = blockIdx.y, b = blockIdx.z;
    const int tid = threadIdx.x, w = tid >> 5, lane = tid & 31;
    const int lq = lane >> 2, lr = lane & 3;
    const int r0 = w * 16 + lq;            // query row within block (0..127)

    const size_t headL = (size_t)(b * HH + h) * LL;
    const size_t headG = (size_t)(b * HH + h) * GG;

    // Q fragments (persistent): rows r0 / r0+8, cols kt*8 + {lr, lr+4}
    float qa[8][4];
    {
        const float* qb = g_q + (headL + (size_t)n * 128) * DH;
#pragma unroll
        for (int kt = 0; kt < 8; kt++) {
            qa[kt][0] = tf32r(qb[(size_t)r0 * DH + kt * 8 + lr]);
            qa[kt][1] = tf32r(qb[(size_t)(r0 + 8) * DH + kt * 8 + lr]);
            qa[kt][2] = tf32r(qb[(size_t)r0 * DH + kt * 8 + lr + 4]);
            qa[kt][3] = tf32r(qb[(size_t)(r0 + 8) * DH + kt * 8 + lr + 4]);
        }
    }

    float m0 = -1e30f, m1 = -1e30f;        // running maxima (rows r0, r0+8)
    float d0 = 0.f, d1 = 0.f;              // lane-partial denominators
    float acc[8][4];
#pragma unroll
    for (int j = 0; j < 8; j++)
#pragma unroll
        for (int e = 0; e < 4; e++) acc[j][e] = 0.f;

#pragma unroll 1
    for (int chnk = 0; chnk < 5; chnk++) {
        const float *kp, *vp;
        if (chnk < 3) {
            int nb2 = n - 1 + chnk;
            if (nb2 < 0 || nb2 >= 32) continue;        // padded / OOB block
            kp = g_k + (headL + (size_t)nb2 * 128) * DH;
            vp = g_v + (headL + (size_t)nb2 * 128) * DH;
        } else {
            kp = g_sk + (headG + (size_t)(chnk - 3) * 128) * DH;
            vp = g_sv + (headG + (size_t)(chnk - 3) * 128) * DH;
        }

        __syncthreads();   // previous chunk's smem fully consumed
        // Load K,V chunk [128,64] -> smem (tf32-rounded)
#pragma unroll
        for (int i = 0; i < 8; i++) {
            int idx = tid + i * 256;
            int row = idx >> 4, c4 = (idx & 15) << 2;
            float4 kk4 = *(const float4*)(kp + (size_t)row * DH + c4);
            float4 vv4 = *(const float4*)(vp + (size_t)row * DH + c4);
            float4 t;
            t.x = tf32r(kk4.x); t.y = tf32r(kk4.y); t.z = tf32r(kk4.z); t.w = tf32r(kk4.w);
            *(float4*)(Ks + row * KS_STRIDE + c4) = t;
            t.x = tf32r(vv4.x); t.y = tf32r(vv4.y); t.z = tf32r(vv4.z); t.w = tf32r(vv4.w);
            *(float4*)(Vs + row * KS_STRIDE + c4) = t;
        }
        __syncthreads();

        // S = Q @ K^T : per warp [16,128] over 16 n-tiles
        float s[16][4];
#pragma unroll
        for (int nt = 0; nt < 16; nt++) {
            s[nt][0] = s[nt][1] = s[nt][2] = s[nt][3] = 0.f;
#pragma unroll
            for (int ks = 0; ks < 8; ks++) {
                float b0 = Ks[(nt * 8 + lq) * KS_STRIDE + ks * 8 + lr];
                float b1 = Ks[(nt * 8 + lq) * KS_STRIDE + ks * 8 + lr + 4];
                mma_tf32(s[nt], qa[ks][0], qa[ks][1], qa[ks][2], qa[ks][3], b0, b1);
            }
        }

        // Banded mask: prev block valid iff k>=q+1; next block valid iff k<=q-1
        if (chnk == 0 || chnk == 2) {
#pragma unroll
            for (int nt = 0; nt < 16; nt++) {
                int k0 = nt * 8 + 2 * lr, k1 = k0 + 1;
                if (chnk == 0) {
                    if (k0 < r0 + 1) s[nt][0] = -1e30f;
                    if (k1 < r0 + 1) s[nt][1] = -1e30f;
                    if (k0 < r0 + 9) s[nt][2] = -1e30f;
                    if (k1 < r0 + 9) s[nt][3] = -1e30f;
                } else {
                    if (k0 > r0 - 1) s[nt][0] = -1e30f;
                    if (k1 > r0 - 1) s[nt][1] = -1e30f;
                    if (k0 > r0 + 7) s[nt][2] = -1e30f;
                    if (k1 > r0 + 7) s[nt][3] = -1e30f;
                }
            }
        }

        // Online softmax update
        float cm0 = -1e30f, cm1 = -1e30f;
#pragma unroll
        for (int nt = 0; nt < 16; nt++) {
            cm0 = fmaxf(cm0, fmaxf(s[nt][0], s[nt][1]));
            cm1 = fmaxf(cm1, fmaxf(s[nt][2], s[nt][3]));
        }
        cm0 = fmaxf(cm0, __shfl_xor_sync(0xffffffffu, cm0, 1));
        cm0 = fmaxf(cm0, __shfl_xor_sync(0xffffffffu, cm0, 2));
        cm1 = fmaxf(cm1, __shfl_xor_sync(0xffffffffu, cm1, 1));
        cm1 = fmaxf(cm1, __shfl_xor_sync(0xffffffffu, cm1, 2));
        float nm0 = fmaxf(m0, cm0), nm1 = fmaxf(m1, cm1);
        float sc0 = __expf(m0 - nm0), sc1 = __expf(m1 - nm1);
        d0 *= sc0; d1 *= sc1;
#pragma unroll
        for (int nj = 0; nj < 8; nj++) {
            acc[nj][0] *= sc0; acc[nj][1] *= sc0;
            acc[nj][2] *= sc1; acc[nj][3] *= sc1;
        }
        m0 = nm0; m1 = nm1;

        float ps0 = 0.f, ps1 = 0.f;
#pragma unroll
        for (int nt = 0; nt < 16; nt++) {
            float p0 = __expf(s[nt][0] - nm0);
            float p1 = __expf(s[nt][1] - nm0);
            float p2 = __expf(s[nt][2] - nm1);
            float p3 = __expf(s[nt][3] - nm1);
            ps0 += p0 + p1; ps1 += p2 + p3;
            float2 o;
            o.x = tf32r(p0); o.y = tf32r(p1);
            *(float2*)(Ps + r0 * PS_STRIDE + nt * 8 + 2 * lr) = o;
            o.x = tf32r(p2); o.y = tf32r(p3);
            *(float2*)(Ps + (r0 + 8) * PS_STRIDE + nt * 8 + 2 * lr) = o;
        }
        d0 += ps0; d1 += ps1;
        __syncwarp();   // each warp only reads its own P rows below

        // acc += P @ V : per warp [16,64]
#pragma unroll
        for (int kt = 0; kt < 16; kt++) {
            float a0 = Ps[r0 * PS_STRIDE + kt * 8 + lr];
            float a1 = Ps[(r0 + 8) * PS_STRIDE + kt * 8 + lr];
            float a2 = Ps[r0 * PS_STRIDE + kt * 8 + lr + 4];
            float a3 = Ps[(r0 + 8) * PS_STRIDE + kt * 8 + lr + 4];
#pragma unroll
            for (int nj = 0; nj < 8; nj++) {
                float b0 = Vs[(kt * 8 + lr) * KS_STRIDE + nj * 8 + lq];
                float b1 = Vs[(kt * 8 + lr + 4) * KS_STRIDE + nj * 8 + lq];
                mma_tf32(acc[nj], a0, a1, a2, a3, b0, b1);
            }
        }
    }

    // Finalize: denom = sum over quad lanes + exp(-running_max)
    float dt0 = d0 + __shfl_xor_sync(0xffffffffu, d0, 1);
    dt0 += __shfl_xor_sync(0xffffffffu, dt0, 2);
    float dt1 = d1 + __shfl_xor_sync(0xffffffffu, d1, 1);
    dt1 += __shfl_xor_sync(0xffffffffu, dt1, 2);
    dt0 += __expf(-m0);
    dt1 += __expf(-m1);
    float inv0 = 1.f / dt0, inv1 = 1.f / dt1;

    float* yb = g_y + ((size_t)b * LL + (size_t)n * 128) * HD + h * DH;
#pragma unroll
    for (int nj = 0; nj < 8; nj++) {
        float2 o;
        o.x = acc[nj][0] * inv0; o.y = acc[nj][1] * inv0;
        *(float2*)(yb + (size_t)r0 * HD + nj * 8 + 2 * lr) = o;
        o.x = acc[nj][2] * inv1; o.y = acc[nj][3] * inv1;
        *(float2*)(yb + (size_t)(r0 + 8) * HD + nj * 8 + 2 * lr) = o;
    }
}

// ---------------------------------------------------------------------------
// Launch
// ---------------------------------------------------------------------------
extern "C" void kernel_launch(void* const* d_in, const int* in_sizes, int n_in,
                              void* d_out, int out_size)
{
    const float* x  = (const float*)d_in[0];
    const float* Wq = (const float*)d_in[1];
    const float* Wk = (const float*)d_in[2];
    const float* Wv = (const float*)d_in[3];
    const float* Wo = (const float*)d_in[4];
    float* out = (float*)d_out;

    cudaFuncSetAttribute(attn_kernel,
                         cudaFuncAttributeMaxDynamicSharedMemorySize,
                         ATTN_SMEM_BYTES);

    // 1) 16-token block sums g
    k_gsum<<<2048, 256>>>(x);

    // 2) fused QKV + side projections: M=8704 (x rows + g rows), N=3072
    gemm_tf32<0><<<dim3(24, 68), 256>>>(x, Wq, Wk, Wv, nullptr);

    // 3) attention: one CTA per (block, head, batch)
    attn_kernel<<<dim3(32, 16, 2), 256, ATTN_SMEM_BYTES>>>();

    // 4) output projection: M=8192, N=1024
    gemm_tf32<1><<<dim3(8, 64), 256>>>(nullptr, Wo, nullptr, nullptr, out);
}

// round 2
// speedup vs baseline: 1.0711x; 1.0711x over previous
#include <cuda_runtime.h>
#include <cstdint>

// Problem constants
#define BB 2
#define LL 4096
#define DD 1024
#define HH 16
#define DH 64
#define GG 256
#define HD 1024   // H*dh

// ---------------------------------------------------------------------------
// Scratch (device globals; allocation inside kernel_launch is forbidden)
// ---------------------------------------------------------------------------
__device__ float g_q [BB*HH*LL*DH];   // [B,H,L,dh]  (pre-scaled by 1/8)
__device__ float g_k [BB*HH*LL*DH];   // [B,H,L,dh]
__device__ float g_v [BB*HH*LL*DH];   // [B,H,L,dh]
__device__ float g_sk[BB*HH*GG*DH];   // [B,H,G,dh]
__device__ float g_sv[BB*HH*GG*DH];   // [B,H,G,dh]
__device__ float g_g [BB*GG*DD];      // [B,G,D]  block sums of x
__device__ float g_y [BB*LL*HD];      // [B,L,H*dh] attention output

// ---------------------------------------------------------------------------
// Helpers
// ---------------------------------------------------------------------------
__device__ __forceinline__ float tf32r(float x) {
    uint32_t u;
    asm("cvt.rna.tf32.f32 %0, %1;" : "=r"(u) : "f"(x));
    return __uint_as_float(u);
}

__device__ __forceinline__ void mma_tf32(float* c,
                                         float a0, float a1, float a2, float a3,
                                         float b0, float b1) {
    asm volatile(
        "mma.sync.aligned.m16n8k8.row.col.f32.tf32.tf32.f32 "
        "{%0,%1,%2,%3}, {%4,%5,%6,%7}, {%8,%9}, {%0,%1,%2,%3};\n"
        : "+f"(c[0]), "+f"(c[1]), "+f"(c[2]), "+f"(c[3])
        : "r"(__float_as_uint(a0)), "r"(__float_as_uint(a1)),
          "r"(__float_as_uint(a2)), "r"(__float_as_uint(a3)),
          "r"(__float_as_uint(b0)), "r"(__float_as_uint(b1)));
}

// ---------------------------------------------------------------------------
// Kernel 1: g[b,gb,d] = sum_{t<16} x[b, gb*16+t, d]
// ---------------------------------------------------------------------------
__global__ void k_gsum(const float* __restrict__ x) {
    int idx = blockIdx.x * blockDim.x + threadIdx.x;     // 524288 threads
    int d   = idx & 1023;
    int row = idx >> 10;            // b*256 + gb
    int b   = row >> 8;
    int gb  = row & 255;
    const float* xp = x + ((size_t)b * LL + gb * 16) * DD + d;
    float s = 0.f;
#pragma unroll
    for (int t = 0; t < 16; t++) s += xp[(size_t)t * DD];
    g_g[idx] = s;
}

// ---------------------------------------------------------------------------
// tf32 GEMM, CTA tile 128(m) x 256(n) x 16(k), 8 warps (2m x 4n),
// warp tile 64x64 (4 m-tiles x 8 n-tiles of m16n8k8).
// Dynamic smem: As[2][16][136] then Bs[2][16][264] (both pad ≡8 mod 32).
// MODE 0: A = [x ; g] (M=8704, K=1024), B = [Wq|Wk|Wv] (N=3072),
//         scatter into g_q/g_k/g_v/g_sk/g_sv, q scaled by 1/8.
// MODE 1: A = g_y (M=8192), B = Wo (N=1024) -> Out.
// ---------------------------------------------------------------------------
#define AS_STRIDE 136
#define BS_STRIDE 264
#define GEMM_SMEM_FLOATS (2*16*AS_STRIDE + 2*16*BS_STRIDE)
#define GEMM_SMEM_BYTES  (GEMM_SMEM_FLOATS * 4)

template<int MODE>
__global__ void __launch_bounds__(256, 1)
gemm_tf32(const float* __restrict__ X,
          const float* __restrict__ W0,
          const float* __restrict__ W1,
          const float* __restrict__ W2,
          float* __restrict__ Out)
{
    extern __shared__ float smg[];
    float* As = smg;                        // [2][16][136]
    float* Bs = smg + 2 * 16 * AS_STRIDE;   // [2][16][264]

    const int bn = blockIdx.x, bm = blockIdx.y;
    const int tid  = threadIdx.x;
    const int warp = tid >> 5, lane = tid & 31;
    const int lq = lane >> 2, lr = lane & 3;
    const int wm = warp >> 2;               // 0..1
    const int wn = warp & 3;                // 0..3

    const int mbase = bm * 128;
    const int nbase = bn * 256;

    const float* Aptr;
    const float* Wp;
    int which = 0;
    if (MODE == 0) {
        Aptr = (mbase < 8192) ? (X + (size_t)mbase * DD)
                              : (g_g + (size_t)(mbase - 8192) * DD);
        which = nbase >> 10;
        Wp = (which == 0) ? W0 : (which == 1) ? W1 : W2;
        Wp += (nbase & 1023);
    } else {
        Aptr = g_y + (size_t)mbase * HD;
        Wp   = W0 + nbase;
    }

    float c[4][8][4];
#pragma unroll
    for (int i = 0; i < 4; i++)
#pragma unroll
        for (int j = 0; j < 8; j++)
#pragma unroll
            for (int e = 0; e < 4; e++) c[i][j][e] = 0.f;

    // A loader: thread -> rows am, am+64 ; k = ak..ak+3
    const int am  = tid >> 2;            // 0..63
    const int ak  = (tid & 3) << 2;      // 0,4,8,12
    // B loader: thread -> k rows bk4..bk4+3 ; n = bn4..bn4+3
    const int bk4 = (tid >> 6) << 2;     // 0,4,8,12
    const int bn4 = (tid & 63) << 2;     // 0..252

    float4 ra0, ra1, rb[4];

#define LDG_TILE(kt) do {                                                     \
        const float* ap = Aptr + (kt) * 16;                                   \
        ra0 = *(const float4*)(ap + (size_t)am * 1024 + ak);                  \
        ra1 = *(const float4*)(ap + (size_t)(am + 64) * 1024 + ak);           \
        const float* bp = Wp + (size_t)((kt) * 16) * 1024;                    \
        _Pragma("unroll")                                                     \
        for (int j = 0; j < 4; j++)                                           \
            rb[j] = *(const float4*)(bp + (size_t)(bk4 + j) * 1024 + bn4);    \
    } while (0)

#define STS_TILE(buf) do {                                                    \
        const float* pa0 = (const float*)&ra0;                                \
        const float* pa1 = (const float*)&ra1;                                \
        _Pragma("unroll")                                                     \
        for (int j = 0; j < 4; j++) {                                         \
            As[(buf)*16*AS_STRIDE + (ak + j)*AS_STRIDE + am]      = tf32r(pa0[j]); \
            As[(buf)*16*AS_STRIDE + (ak + j)*AS_STRIDE + am + 64] = tf32r(pa1[j]); \
        }                                                                     \
        _Pragma("unroll")                                                     \
        for (int j = 0; j < 4; j++) {                                         \
            float4 t;                                                         \
            t.x = tf32r(rb[j].x); t.y = tf32r(rb[j].y);                       \
            t.z = tf32r(rb[j].z); t.w = tf32r(rb[j].w);                       \
            *(float4*)&Bs[(buf)*16*BS_STRIDE + (bk4 + j)*BS_STRIDE + bn4] = t; \
        }                                                                     \
    } while (0)

    const int NK = 64;                   // K = 1024 / 16
    LDG_TILE(0);
    STS_TILE(0);
    __syncthreads();

    for (int kt = 0; kt < NK; kt++) {
        const int buf = kt & 1;
        if (kt + 1 < NK) LDG_TILE(kt + 1);

        const float* Ab = As + buf * 16 * AS_STRIDE;
        const float* Bb = Bs + buf * 16 * BS_STRIDE;
#pragma unroll
        for (int ks = 0; ks < 2; ks++) {
            float a[4][4], bfr[8][2];
#pragma unroll
            for (int mi = 0; mi < 4; mi++) {
                int r = wm * 64 + mi * 16 + lq;
                a[mi][0] = Ab[(ks * 8 + lr) * AS_STRIDE + r];
                a[mi][1] = Ab[(ks * 8 + lr) * AS_STRIDE + r + 8];
                a[mi][2] = Ab[(ks * 8 + lr + 4) * AS_STRIDE + r];
                a[mi][3] = Ab[(ks * 8 + lr + 4) * AS_STRIDE + r + 8];
            }
#pragma unroll
            for (int nj = 0; nj < 8; nj++) {
                int cc = wn * 64 + nj * 8 + lq;
                bfr[nj][0] = Bb[(ks * 8 + lr) * BS_STRIDE + cc];
                bfr[nj][1] = Bb[(ks * 8 + lr + 4) * BS_STRIDE + cc];
            }
#pragma unroll
            for (int mi = 0; mi < 4; mi++)
#pragma unroll
                for (int nj = 0; nj < 8; nj++)
                    mma_tf32(c[mi][nj], a[mi][0], a[mi][1], a[mi][2], a[mi][3],
                             bfr[nj][0], bfr[nj][1]);
        }

        if (kt + 1 < NK) {
            STS_TILE(buf ^ 1);
            __syncthreads();
        }
    }
#undef LDG_TILE
#undef STS_TILE

    // -------------------------- epilogue --------------------------
#pragma unroll
    for (int mi = 0; mi < 4; mi++)
#pragma unroll
        for (int e2 = 0; e2 < 2; e2++) {
            int gm = mbase + wm * 64 + mi * 16 + lq + e2 * 8;
#pragma unroll
            for (int nj = 0; nj < 8; nj++) {
                float v0 = c[mi][nj][e2 * 2 + 0];
                float v1 = c[mi][nj][e2 * 2 + 1];
                if (MODE == 1) {
                    int gn = nbase + wn * 64 + nj * 8 + 2 * lr;
                    float2 o; o.x = v0; o.y = v1;
                    *(float2*)(Out + (size_t)gm * 1024 + gn) = o;
                } else {
                    int cc = (nbase & 1023) + wn * 64 + nj * 8 + 2 * lr;
                    int h  = cc >> 6;
                    int chc = cc & 63;
                    if (gm < 8192) {
                        int b = gm >> 12, l = gm & 4095;
                        float s = (which == 0) ? 0.125f : 1.0f;
                        float* dst = (which == 0) ? g_q : (which == 1) ? g_k : g_v;
                        dst += ((size_t)(b * HH + h) * LL + l) * DH + chc;
                        float2 o; o.x = v0 * s; o.y = v1 * s;
                        *(float2*)dst = o;
                    } else if (which != 0) {
                        int gb = gm - 8192;
                        int b = gb >> 8, gp = gb & 255;
                        float* dst = (which == 1) ? g_sk : g_sv;
                        dst += ((size_t)(b * HH + h) * GG + gp) * DH + chc;
                        float2 o; o.x = v0; o.y = v1;
                        *(float2*)dst = o;
                    }
                }
            }
        }
}

// ---------------------------------------------------------------------------
// Kernel 3: attention (unchanged from R1).
// ---------------------------------------------------------------------------
#define KS_STRIDE 72     // 64 + 8
#define PS_STRIDE 136    // 128 + 8
#define ATTN_SMEM_BYTES ((128*KS_STRIDE*2 + 128*PS_STRIDE) * 4)

__global__ void __launch_bounds__(256, 1)
attn_kernel()
{
    extern __shared__ float sm[];
    float* Ks = sm;                        // [128][72]
    float* Vs = sm + 128 * KS_STRIDE;      // [128][72]
    float* Ps = Vs + 128 * KS_STRIDE;      // [128][136]

    const int n = blockIdx.x, h = blockIdx.y, b = blockIdx.z;
    const int tid = threadIdx.x, w = tid >> 5, lane = tid & 31;
    const int lq = lane >> 2, lr = lane & 3;
    const int r0 = w * 16 + lq;            // query row within block (0..127)

    const size_t headL = (size_t)(b * HH + h) * LL;
    const size_t headG = (size_t)(b * HH + h) * GG;

    float qa[8][4];
    {
        const float* qb = g_q + (headL + (size_t)n * 128) * DH;
#pragma unroll
        for (int kt = 0; kt < 8; kt++) {
            qa[kt][0] = tf32r(qb[(size_t)r0 * DH + kt * 8 + lr]);
            qa[kt][1] = tf32r(qb[(size_t)(r0 + 8) * DH + kt * 8 + lr]);
            qa[kt][2] = tf32r(qb[(size_t)r0 * DH + kt * 8 + lr + 4]);
            qa[kt][3] = tf32r(qb[(size_t)(r0 + 8) * DH + kt * 8 + lr + 4]);
        }
    }

    float m0 = -1e30f, m1 = -1e30f;
    float d0 = 0.f, d1 = 0.f;
    float acc[8][4];
#pragma unroll
    for (int j = 0; j < 8; j++)
#pragma unroll
        for (int e = 0; e < 4; e++) acc[j][e] = 0.f;

#pragma unroll 1
    for (int chnk = 0; chnk < 5; chnk++) {
        const float *kp, *vp;
        if (chnk < 3) {
            int nb2 = n - 1 + chnk;
            if (nb2 < 0 || nb2 >= 32) continue;
            kp = g_k + (headL + (size_t)nb2 * 128) * DH;
            vp = g_v + (headL + (size_t)nb2 * 128) * DH;
        } else {
            kp = g_sk + (headG + (size_t)(chnk - 3) * 128) * DH;
            vp = g_sv + (headG + (size_t)(chnk - 3) * 128) * DH;
        }

        __syncthreads();
#pragma unroll
        for (int i = 0; i < 8; i++) {
            int idx = tid + i * 256;
            int row = idx >> 4, c4 = (idx & 15) << 2;
            float4 kk4 = *(const float4*)(kp + (size_t)row * DH + c4);
            float4 vv4 = *(const float4*)(vp + (size_t)row * DH + c4);
            float4 t;
            t.x = tf32r(kk4.x); t.y = tf32r(kk4.y); t.z = tf32r(kk4.z); t.w = tf32r(kk4.w);
            *(float4*)(Ks + row * KS_STRIDE + c4) = t;
            t.x = tf32r(vv4.x); t.y = tf32r(vv4.y); t.z = tf32r(vv4.z); t.w = tf32r(vv4.w);
            *(float4*)(Vs + row * KS_STRIDE + c4) = t;
        }
        __syncthreads();

        float s[16][4];
#pragma unroll
        for (int nt = 0; nt < 16; nt++) {
            s[nt][0] = s[nt][1] = s[nt][2] = s[nt][3] = 0.f;
#pragma unroll
            for (int ks = 0; ks < 8; ks++) {
                float b0 = Ks[(nt * 8 + lq) * KS_STRIDE + ks * 8 + lr];
                float b1 = Ks[(nt * 8 + lq) * KS_STRIDE + ks * 8 + lr + 4];
                mma_tf32(s[nt], qa[ks][0], qa[ks][1], qa[ks][2], qa[ks][3], b0, b1);
            }
        }

        if (chnk == 0 || chnk == 2) {
#pragma unroll
            for (int nt = 0; nt < 16; nt++) {
                int k0 = nt * 8 + 2 * lr, k1 = k0 + 1;
                if (chnk == 0) {
                    if (k0 < r0 + 1) s[nt][0] = -1e30f;
                    if (k1 < r0 + 1) s[nt][1] = -1e30f;
                    if (k0 < r0 + 9) s[nt][2] = -1e30f;
                    if (k1 < r0 + 9) s[nt][3] = -1e30f;
                } else {
                    if (k0 > r0 - 1) s[nt][0] = -1e30f;
                    if (k1 > r0 - 1) s[nt][1] = -1e30f;
                    if (k0 > r0 + 7) s[nt][2] = -1e30f;
                    if (k1 > r0 + 7) s[nt][3] = -1e30f;
                }
            }
        }

        float cm0 = -1e30f, cm1 = -1e30f;
#pragma unroll
        for (int nt = 0; nt < 16; nt++) {
            cm0 = fmaxf(cm0, fmaxf(s[nt][0], s[nt][1]));
            cm1 = fmaxf(cm1, fmaxf(s[nt][2], s[nt][3]));
        }
        cm0 = fmaxf(cm0, __shfl_xor_sync(0xffffffffu, cm0, 1));
        cm0 = fmaxf(cm0, __shfl_xor_sync(0xffffffffu, cm0, 2));
        cm1 = fmaxf(cm1, __shfl_xor_sync(0xffffffffu, cm1, 1));
        cm1 = fmaxf(cm1, __shfl_xor_sync(0xffffffffu, cm1, 2));
        float nm0 = fmaxf(m0, cm0), nm1 = fmaxf(m1, cm1);
        float sc0 = __expf(m0 - nm0), sc1 = __expf(m1 - nm1);
        d0 *= sc0; d1 *= sc1;
#pragma unroll
        for (int nj = 0; nj < 8; nj++) {
            acc[nj][0] *= sc0; acc[nj][1] *= sc0;
            acc[nj][2] *= sc1; acc[nj][3] *= sc1;
        }
        m0 = nm0; m1 = nm1;

        float ps0 = 0.f, ps1 = 0.f;
#pragma unroll
        for (int nt = 0; nt < 16; nt++) {
            float p0 = __expf(s[nt][0] - nm0);
            float p1 = __expf(s[nt][1] - nm0);
            float p2 = __expf(s[nt][2] - nm1);
            float p3 = __expf(s[nt][3] - nm1);
            ps0 += p0 + p1; ps1 += p2 + p3;
            float2 o;
            o.x = tf32r(p0); o.y = tf32r(p1);
            *(float2*)(Ps + r0 * PS_STRIDE + nt * 8 + 2 * lr) = o;
            o.x = tf32r(p2); o.y = tf32r(p3);
            *(float2*)(Ps + (r0 + 8) * PS_STRIDE + nt * 8 + 2 * lr) = o;
        }
        d0 += ps0; d1 += ps1;
        __syncwarp();

#pragma unroll
        for (int kt = 0; kt < 16; kt++) {
            float a0 = Ps[r0 * PS_STRIDE + kt * 8 + lr];
            float a1 = Ps[(r0 + 8) * PS_STRIDE + kt * 8 + lr];
            float a2 = Ps[r0 * PS_STRIDE + kt * 8 + lr + 4];
            float a3 = Ps[(r0 + 8) * PS_STRIDE + kt * 8 + lr + 4];
#pragma unroll
            for (int nj = 0; nj < 8; nj++) {
                float b0 = Vs[(kt * 8 + lr) * KS_STRIDE + nj * 8 + lq];
                float b1 = Vs[(kt * 8 + lr + 4) * KS_STRIDE + nj * 8 + lq];
                mma_tf32(acc[nj], a0, a1, a2, a3, b0, b1);
            }
        }
    }

    float dt0 = d0 + __shfl_xor_sync(0xffffffffu, d0, 1);
    dt0 += __shfl_xor_sync(0xffffffffu, dt0, 2);
    float dt1 = d1 + __shfl_xor_sync(0xffffffffu, d1, 1);
    dt1 += __shfl_xor_sync(0xffffffffu, dt1, 2);
    dt0 += __expf(-m0);
    dt1 += __expf(-m1);
    float inv0 = 1.f / dt0, inv1 = 1.f / dt1;

    float* yb = g_y + ((size_t)b * LL + (size_t)n * 128) * HD + h * DH;
#pragma unroll
    for (int nj = 0; nj < 8; nj++) {
        float2 o;
        o.x = acc[nj][0] * inv0; o.y = acc[nj][1] * inv0;
        *(float2*)(yb + (size_t)r0 * HD + nj * 8 + 2 * lr) = o;
        o.x = acc[nj][2] * inv1; o.y = acc[nj][3] * inv1;
        *(float2*)(yb + (size_t)(r0 + 8) * HD + nj * 8 + 2 * lr) = o;
    }
}

// ---------------------------------------------------------------------------
// Launch
// ---------------------------------------------------------------------------
extern "C" void kernel_launch(void* const* d_in, const int* in_sizes, int n_in,
                              void* d_out, int out_size)
{
    const float* x  = (const float*)d_in[0];
    const float* Wq = (const float*)d_in[1];
    const float* Wk = (const float*)d_in[2];
    const float* Wv = (const float*)d_in[3];
    const float* Wo = (const float*)d_in[4];
    float* out = (float*)d_out;

    cudaFuncSetAttribute(attn_kernel,
                         cudaFuncAttributeMaxDynamicSharedMemorySize,
                         ATTN_SMEM_BYTES);
    cudaFuncSetAttribute(gemm_tf32<0>,
                         cudaFuncAttributeMaxDynamicSharedMemorySize,
                         GEMM_SMEM_BYTES);
    cudaFuncSetAttribute(gemm_tf32<1>,
                         cudaFuncAttributeMaxDynamicSharedMemorySize,
                         GEMM_SMEM_BYTES);

    // 1) 16-token block sums g
    k_gsum<<<2048, 256>>>(x);

    // 2) fused QKV + side projections: M=8704 rows, N=3072 (12 n-blocks of 256)
    gemm_tf32<0><<<dim3(12, 68), 256, GEMM_SMEM_BYTES>>>(x, Wq, Wk, Wv, nullptr);

    // 3) attention: one CTA per (block, head, batch)
    attn_kernel<<<dim3(32, 16, 2), 256, ATTN_SMEM_BYTES>>>();

    // 4) output projection: M=8192, N=1024 (4 n-blocks of 256)
    gemm_tf32<1><<<dim3(4, 64), 256, GEMM_SMEM_BYTES>>>(nullptr, Wo, nullptr, nullptr, out);
}

// round 3
// speedup vs baseline: 1.0934x; 1.0208x over previous
#include <cuda_runtime.h>
#include <cstdint>

// Problem constants
#define BB 2
#define LL 4096
#define DD 1024
#define HH 16
#define DH 64
#define GG 256
#define HD 1024   // H*dh

// ---------------------------------------------------------------------------
// Scratch
// ---------------------------------------------------------------------------
__device__ float g_q [BB*HH*LL*DH];   // [B,H,L,dh]  (pre-scaled by 1/8)
__device__ float g_k [BB*HH*LL*DH];
__device__ float g_v [BB*HH*LL*DH];
__device__ float g_sk[BB*HH*GG*DH];
__device__ float g_sv[BB*HH*GG*DH];
__device__ float g_g [BB*GG*DD];
__device__ float g_y [BB*LL*HD];

// ---------------------------------------------------------------------------
// Helpers
// ---------------------------------------------------------------------------
__device__ __forceinline__ float tf32r(float x) {
    uint32_t u;
    asm("cvt.rna.tf32.f32 %0, %1;" : "=r"(u) : "f"(x));
    return __uint_as_float(u);
}

__device__ __forceinline__ void mma_tf32(float* c,
                                         float a0, float a1, float a2, float a3,
                                         float b0, float b1) {
    asm volatile(
        "mma.sync.aligned.m16n8k8.row.col.f32.tf32.tf32.f32 "
        "{%0,%1,%2,%3}, {%4,%5,%6,%7}, {%8,%9}, {%0,%1,%2,%3};\n"
        : "+f"(c[0]), "+f"(c[1]), "+f"(c[2]), "+f"(c[3])
        : "r"(__float_as_uint(a0)), "r"(__float_as_uint(a1)),
          "r"(__float_as_uint(a2)), "r"(__float_as_uint(a3)),
          "r"(__float_as_uint(b0)), "r"(__float_as_uint(b1)));
}

__device__ __forceinline__ uint32_t smem_u32(const void* p) {
    return (uint32_t)__cvta_generic_to_shared(p);
}
__device__ __forceinline__ void cp16(uint32_t dst, const void* src) {
    asm volatile("cp.async.cg.shared.global [%0], [%1], 16;" :: "r"(dst), "l"(src));
}
__device__ __forceinline__ void cp_commit() {
    asm volatile("cp.async.commit_group;");
}
template<int N>
__device__ __forceinline__ void cp_wait() {
    asm volatile("cp.async.wait_group %0;" :: "n"(N));
}

// ---------------------------------------------------------------------------
// Kernel 1: g[b,gb,d] = sum_{t<16} x[b, gb*16+t, d]
// ---------------------------------------------------------------------------
__global__ void k_gsum(const float* __restrict__ x) {
    int idx = blockIdx.x * blockDim.x + threadIdx.x;
    int d   = idx & 1023;
    int row = idx >> 10;
    int b   = row >> 8;
    int gb  = row & 255;
    const float* xp = x + ((size_t)b * LL + gb * 16) * DD + d;
    float s = 0.f;
#pragma unroll
    for (int t = 0; t < 16; t++) s += xp[(size_t)t * DD];
    g_g[idx] = s;
}

// ---------------------------------------------------------------------------
// tf32 GEMM with cp.async 3-stage pipeline.
// CTA tile 128(m) x 256(n) x 16(k); 8 warps (2m x 4n); warp tile 64x64.
// Smem: As[3][128][20] (A as [m][k], stride 20: conflict-free frag reads)
//       Bs[3][16][264]  (B as [k][n], stride 264 ≡ 8 mod 32)
// tf32 RNA rounding applied at fragment-load time (same values/order as R2).
// ---------------------------------------------------------------------------
#define AS_STRIDE 20
#define BS_STRIDE 264
#define AS_STAGE (128*AS_STRIDE)
#define BS_STAGE (16*BS_STRIDE)
#define GEMM_SMEM_BYTES ((3*AS_STAGE + 3*BS_STAGE) * 4)

template<int MODE>
__global__ void __launch_bounds__(256, 1)
gemm_tf32(const float* __restrict__ X,
          const float* __restrict__ W0,
          const float* __restrict__ W1,
          const float* __restrict__ W2,
          float* __restrict__ Out)
{
    extern __shared__ float smg[];
    float* As = smg;                   // [3][128][20]
    float* Bs = smg + 3 * AS_STAGE;    // [3][16][264]

    const int bn = blockIdx.x, bm = blockIdx.y;
    const int tid  = threadIdx.x;
    const int warp = tid >> 5, lane = tid & 31;
    const int lq = lane >> 2, lr = lane & 3;
    const int wm = warp >> 2;               // 0..1
    const int wn = warp & 3;                // 0..3

    const int mbase = bm * 128;
    const int nbase = bn * 256;

    const float* Aptr;
    const float* Wp;
    int which = 0;
    if (MODE == 0) {
        Aptr = (mbase < 8192) ? (X + (size_t)mbase * DD)
                              : (g_g + (size_t)(mbase - 8192) * DD);
        which = nbase >> 10;
        Wp = (which == 0) ? W0 : (which == 1) ? W1 : W2;
        Wp += (nbase & 1023);
    } else {
        Aptr = g_y + (size_t)mbase * HD;
        Wp   = W0 + nbase;
    }

    float c[4][8][4];
#pragma unroll
    for (int i = 0; i < 4; i++)
#pragma unroll
        for (int j = 0; j < 8; j++)
#pragma unroll
            for (int e = 0; e < 4; e++) c[i][j][e] = 0.f;

    // A loader: rows am, am+64 ; k = ak..ak+3 (one 16B cp each)
    const int am  = tid >> 2;            // 0..63
    const int ak  = (tid & 3) << 2;      // 0,4,8,12
    // B loader: k rows bk4..bk4+3 ; n cols bn4..bn4+3
    const int bk4 = (tid >> 6) << 2;     // 0,4,8,12
    const int bn4 = (tid & 63) << 2;     // 0..252

    const uint32_t asA0 = smem_u32(As + am * AS_STRIDE + ak);
    const uint32_t asA1 = smem_u32(As + (am + 64) * AS_STRIDE + ak);
    const uint32_t asB  = smem_u32(Bs + bk4 * BS_STRIDE + bn4);

#define ISSUE_TILE(kt, stg) do {                                              \
        const float* ap = Aptr + (kt) * 16;                                   \
        uint32_t aoff = (stg) * (AS_STAGE * 4);                               \
        cp16(asA0 + aoff, ap + (size_t)am * 1024 + ak);                       \
        cp16(asA1 + aoff, ap + (size_t)(am + 64) * 1024 + ak);                \
        const float* bp = Wp + (size_t)((kt) * 16) * 1024;                    \
        uint32_t boff = (stg) * (BS_STAGE * 4);                               \
        _Pragma("unroll")                                                     \
        for (int j = 0; j < 4; j++)                                           \
            cp16(asB + boff + j * (BS_STRIDE * 4),                            \
                 bp + (size_t)(bk4 + j) * 1024 + bn4);                        \
    } while (0)

    const int NK = 64;                   // K = 1024 / 16
    ISSUE_TILE(0, 0); cp_commit();
    ISSUE_TILE(1, 1); cp_commit();

    int stage = 0;
#pragma unroll 1
    for (int kt = 0; kt < NK; kt++) {
        cp_wait<1>();
        __syncthreads();

        if (kt + 2 < NK) {
            int ns = stage + 2; if (ns >= 3) ns -= 3;
            ISSUE_TILE(kt + 2, ns);
        }
        cp_commit();

        const float* Ab = As + stage * AS_STAGE;
        const float* Bb = Bs + stage * BS_STAGE;
#pragma unroll
        for (int ks = 0; ks < 2; ks++) {
            float a[4][4], bfr[8][2];
#pragma unroll
            for (int mi = 0; mi < 4; mi++) {
                int r = wm * 64 + mi * 16 + lq;
                a[mi][0] = tf32r(Ab[r * AS_STRIDE + ks * 8 + lr]);
                a[mi][1] = tf32r(Ab[(r + 8) * AS_STRIDE + ks * 8 + lr]);
                a[mi][2] = tf32r(Ab[r * AS_STRIDE + ks * 8 + lr + 4]);
                a[mi][3] = tf32r(Ab[(r + 8) * AS_STRIDE + ks * 8 + lr + 4]);
            }
#pragma unroll
            for (int nj = 0; nj < 8; nj++) {
                int cc = wn * 64 + nj * 8 + lq;
                bfr[nj][0] = tf32r(Bb[(ks * 8 + lr) * BS_STRIDE + cc]);
                bfr[nj][1] = tf32r(Bb[(ks * 8 + lr + 4) * BS_STRIDE + cc]);
            }
#pragma unroll
            for (int mi = 0; mi < 4; mi++)
#pragma unroll
                for (int nj = 0; nj < 8; nj++)
                    mma_tf32(c[mi][nj], a[mi][0], a[mi][1], a[mi][2], a[mi][3],
                             bfr[nj][0], bfr[nj][1]);
        }

        stage++; if (stage >= 3) stage = 0;
    }
#undef ISSUE_TILE

    // -------------------------- epilogue --------------------------
#pragma unroll
    for (int mi = 0; mi < 4; mi++)
#pragma unroll
        for (int e2 = 0; e2 < 2; e2++) {
            int gm = mbase + wm * 64 + mi * 16 + lq + e2 * 8;
#pragma unroll
            for (int nj = 0; nj < 8; nj++) {
                float v0 = c[mi][nj][e2 * 2 + 0];
                float v1 = c[mi][nj][e2 * 2 + 1];
                if (MODE == 1) {
                    int gn = nbase + wn * 64 + nj * 8 + 2 * lr;
                    float2 o; o.x = v0; o.y = v1;
                    *(float2*)(Out + (size_t)gm * 1024 + gn) = o;
                } else {
                    int cc = (nbase & 1023) + wn * 64 + nj * 8 + 2 * lr;
                    int h  = cc >> 6;
                    int chc = cc & 63;
                    if (gm < 8192) {
                        int b = gm >> 12, l = gm & 4095;
                        float s = (which == 0) ? 0.125f : 1.0f;
                        float* dst = (which == 0) ? g_q : (which == 1) ? g_k : g_v;
                        dst += ((size_t)(b * HH + h) * LL + l) * DH + chc;
                        float2 o; o.x = v0 * s; o.y = v1 * s;
                        *(float2*)dst = o;
                    } else if (which != 0) {
                        int gb = gm - 8192;
                        int b = gb >> 8, gp = gb & 255;
                        float* dst = (which == 1) ? g_sk : g_sv;
                        dst += ((size_t)(b * HH + h) * GG + gp) * DH + chc;
                        float2 o; o.x = v0; o.y = v1;
                        *(float2*)dst = o;
                    }
                }
            }
        }
}

// ---------------------------------------------------------------------------
// Kernel 3: attention (unchanged).
// ---------------------------------------------------------------------------
#define KS_STRIDE 72
#define PS_STRIDE 136
#define ATTN_SMEM_BYTES ((128*KS_STRIDE*2 + 128*PS_STRIDE) * 4)

__global__ void __launch_bounds__(256, 1)
attn_kernel()
{
    extern __shared__ float sm[];
    float* Ks = sm;
    float* Vs = sm + 128 * KS_STRIDE;
    float* Ps = Vs + 128 * KS_STRIDE;

    const int n = blockIdx.x, h = blockIdx.y, b = blockIdx.z;
    const int tid = threadIdx.x, w = tid >> 5, lane = tid & 31;
    const int lq = lane >> 2, lr = lane & 3;
    const int r0 = w * 16 + lq;

    const size_t headL = (size_t)(b * HH + h) * LL;
    const size_t headG = (size_t)(b * HH + h) * GG;

    float qa[8][4];
    {
        const float* qb = g_q + (headL + (size_t)n * 128) * DH;
#pragma unroll
        for (int kt = 0; kt < 8; kt++) {
            qa[kt][0] = tf32r(qb[(size_t)r0 * DH + kt * 8 + lr]);
            qa[kt][1] = tf32r(qb[(size_t)(r0 + 8) * DH + kt * 8 + lr]);
            qa[kt][2] = tf32r(qb[(size_t)r0 * DH + kt * 8 + lr + 4]);
            qa[kt][3] = tf32r(qb[(size_t)(r0 + 8) * DH + kt * 8 + lr + 4]);
        }
    }

    float m0 = -1e30f, m1 = -1e30f;
    float d0 = 0.f, d1 = 0.f;
    float acc[8][4];
#pragma unroll
    for (int j = 0; j < 8; j++)
#pragma unroll
        for (int e = 0; e < 4; e++) acc[j][e] = 0.f;

#pragma unroll 1
    for (int chnk = 0; chnk < 5; chnk++) {
        const float *kp, *vp;
        if (chnk < 3) {
            int nb2 = n - 1 + chnk;
            if (nb2 < 0 || nb2 >= 32) continue;
            kp = g_k + (headL + (size_t)nb2 * 128) * DH;
            vp = g_v + (headL + (size_t)nb2 * 128) * DH;
        } else {
            kp = g_sk + (headG + (size_t)(chnk - 3) * 128) * DH;
            vp = g_sv + (headG + (size_t)(chnk - 3) * 128) * DH;
        }

        __syncthreads();
#pragma unroll
        for (int i = 0; i < 8; i++) {
            int idx = tid + i * 256;
            int row = idx >> 4, c4 = (idx & 15) << 2;
            float4 kk4 = *(const float4*)(kp + (size_t)row * DH + c4);
            float4 vv4 = *(const float4*)(vp + (size_t)row * DH + c4);
            float4 t;
            t.x = tf32r(kk4.x); t.y = tf32r(kk4.y); t.z = tf32r(kk4.z); t.w = tf32r(kk4.w);
            *(float4*)(Ks + row * KS_STRIDE + c4) = t;
            t.x = tf32r(vv4.x); t.y = tf32r(vv4.y); t.z = tf32r(vv4.z); t.w = tf32r(vv4.w);
            *(float4*)(Vs + row * KS_STRIDE + c4) = t;
        }
        __syncthreads();

        float s[16][4];
#pragma unroll
        for (int nt = 0; nt < 16; nt++) {
            s[nt][0] = s[nt][1] = s[nt][2] = s[nt][3] = 0.f;
#pragma unroll
            for (int ks = 0; ks < 8; ks++) {
                float b0 = Ks[(nt * 8 + lq) * KS_STRIDE + ks * 8 + lr];
                float b1 = Ks[(nt * 8 + lq) * KS_STRIDE + ks * 8 + lr + 4];
                mma_tf32(s[nt], qa[ks][0], qa[ks][1], qa[ks][2], qa[ks][3], b0, b1);
            }
        }

        if (chnk == 0 || chnk == 2) {
#pragma unroll
            for (int nt = 0; nt < 16; nt++) {
                int k0 = nt * 8 + 2 * lr, k1 = k0 + 1;
                if (chnk == 0) {
                    if (k0 < r0 + 1) s[nt][0] = -1e30f;
                    if (k1 < r0 + 1) s[nt][1] = -1e30f;
                    if (k0 < r0 + 9) s[nt][2] = -1e30f;
                    if (k1 < r0 + 9) s[nt][3] = -1e30f;
                } else {
                    if (k0 > r0 - 1) s[nt][0] = -1e30f;
                    if (k1 > r0 - 1) s[nt][1] = -1e30f;
                    if (k0 > r0 + 7) s[nt][2] = -1e30f;
                    if (k1 > r0 + 7) s[nt][3] = -1e30f;
                }
            }
        }

        float cm0 = -1e30f, cm1 = -1e30f;
#pragma unroll
        for (int nt = 0; nt < 16; nt++) {
            cm0 = fmaxf(cm0, fmaxf(s[nt][0], s[nt][1]));
            cm1 = fmaxf(cm1, fmaxf(s[nt][2], s[nt][3]));
        }
        cm0 = fmaxf(cm0, __shfl_xor_sync(0xffffffffu, cm0, 1));
        cm0 = fmaxf(cm0, __shfl_xor_sync(0xffffffffu, cm0, 2));
        cm1 = fmaxf(cm1, __shfl_xor_sync(0xffffffffu, cm1, 1));
        cm1 = fmaxf(cm1, __shfl_xor_sync(0xffffffffu, cm1, 2));
        float nm0 = fmaxf(m0, cm0), nm1 = fmaxf(m1, cm1);
        float sc0 = __expf(m0 - nm0), sc1 = __expf(m1 - nm1);
        d0 *= sc0; d1 *= sc1;
#pragma unroll
        for (int nj = 0; nj < 8; nj++) {
            acc[nj][0] *= sc0; acc[nj][1] *= sc0;
            acc[nj][2] *= sc1; acc[nj][3] *= sc1;
        }
        m0 = nm0; m1 = nm1;

        float ps0 = 0.f, ps1 = 0.f;
#pragma unroll
        for (int nt = 0; nt < 16; nt++) {
            float p0 = __expf(s[nt][0] - nm0);
            float p1 = __expf(s[nt][1] - nm0);
            float p2 = __expf(s[nt][2] - nm1);
            float p3 = __expf(s[nt][3] - nm1);
            ps0 += p0 + p1; ps1 += p2 + p3;
            float2 o;
            o.x = tf32r(p0); o.y = tf32r(p1);
            *(float2*)(Ps + r0 * PS_STRIDE + nt * 8 + 2 * lr) = o;
            o.x = tf32r(p2); o.y = tf32r(p3);
            *(float2*)(Ps + (r0 + 8) * PS_STRIDE + nt * 8 + 2 * lr) = o;
        }
        d0 += ps0; d1 += ps1;
        __syncwarp();

#pragma unroll
        for (int kt = 0; kt < 16; kt++) {
            float a0 = Ps[r0 * PS_STRIDE + kt * 8 + lr];
            float a1 = Ps[(r0 + 8) * PS_STRIDE + kt * 8 + lr];
            float a2 = Ps[r0 * PS_STRIDE + kt * 8 + lr + 4];
            float a3 = Ps[(r0 + 8) * PS_STRIDE + kt * 8 + lr + 4];
#pragma unroll
            for (int nj = 0; nj < 8; nj++) {
                float b0 = Vs[(kt * 8 + lr) * KS_STRIDE + nj * 8 + lq];
                float b1 = Vs[(kt * 8 + lr + 4) * KS_STRIDE + nj * 8 + lq];
                mma_tf32(acc[nj], a0, a1, a2, a3, b0, b1);
            }
        }
    }

    float dt0 = d0 + __shfl_xor_sync(0xffffffffu, d0, 1);
    dt0 += __shfl_xor_sync(0xffffffffu, dt0, 2);
    float dt1 = d1 + __shfl_xor_sync(0xffffffffu, d1, 1);
    dt1 += __shfl_xor_sync(0xffffffffu, dt1, 2);
    dt0 += __expf(-m0);
    dt1 += __expf(-m1);
    float inv0 = 1.f / dt0, inv1 = 1.f / dt1;

    float* yb = g_y + ((size_t)b * LL + (size_t)n * 128) * HD + h * DH;
#pragma unroll
    for (int nj = 0; nj < 8; nj++) {
        float2 o;
        o.x = acc[nj][0] * inv0; o.y = acc[nj][1] * inv0;
        *(float2*)(yb + (size_t)r0 * HD + nj * 8 + 2 * lr) = o;
        o.x = acc[nj][2] * inv1; o.y = acc[nj][3] * inv1;
        *(float2*)(yb + (size_t)(r0 + 8) * HD + nj * 8 + 2 * lr) = o;
    }
}

// ---------------------------------------------------------------------------
// Launch
// ---------------------------------------------------------------------------
extern "C" void kernel_launch(void* const* d_in, const int* in_sizes, int n_in,
                              void* d_out, int out_size)
{
    const float* x  = (const float*)d_in[0];
    const float* Wq = (const float*)d_in[1];
    const float* Wk = (const float*)d_in[2];
    const float* Wv = (const float*)d_in[3];
    const float* Wo = (const float*)d_in[4];
    float* out = (float*)d_out;

    cudaFuncSetAttribute(attn_kernel,
                         cudaFuncAttributeMaxDynamicSharedMemorySize,
                         ATTN_SMEM_BYTES);
    cudaFuncSetAttribute(gemm_tf32<0>,
                         cudaFuncAttributeMaxDynamicSharedMemorySize,
                         GEMM_SMEM_BYTES);
    cudaFuncSetAttribute(gemm_tf32<1>,
                         cudaFuncAttributeMaxDynamicSharedMemorySize,
                         GEMM_SMEM_BYTES);

    k_gsum<<<2048, 256>>>(x);
    gemm_tf32<0><<<dim3(12, 68), 256, GEMM_SMEM_BYTES>>>(x, Wq, Wk, Wv, nullptr);
    attn_kernel<<<dim3(32, 16, 2), 256, ATTN_SMEM_BYTES>>>();
    gemm_tf32<1><<<dim3(4, 64), 256, GEMM_SMEM_BYTES>>>(nullptr, Wo, nullptr, nullptr, out);
}